// round 9
// baseline (speedup 1.0000x reference)
#include <cuda_runtime.h>
#include <math.h>

#define IN_DIM   8192
#define OUT_DIM  8192
#define BATCH    8192
#define ROWS     2            // batch rows per tile (64 KB)
#define NBUF     3            // 3 buffers, 2 tiles in flight
#define THREADS  1024
#define COLS_PT  (OUT_DIM / THREADS)   // 8 columns per thread
#define GRID     152          // one persistent CTA per GB300 SM

// GATE_COEFFS, 16 x 4
__constant__ float GC[16][4] = {
    {0, 0, 0, 0}, {0, 0, 0, 1}, {0, 1, 0, -1}, {0, 1, 0, 0},
    {0, 0, 1, -1}, {0, 0, 1, 0}, {0, 1, 1, -2}, {0, 1, 1, -1},
    {1, -1, -1, 1}, {1, -1, -1, 2}, {1, 0, -1, 0}, {1, 0, -1, 1},
    {1, -1, 0, 0}, {1, -1, 0, 1}, {1, 0, 0, -1}, {1, 0, 0, 0}
};

#define TILE_F   (ROWS * IN_DIM)           // floats per tile
extern __shared__ float smem[];            // NBUF * TILE_F floats = 192 KB

__device__ __forceinline__ void stage_tile(int buf, int tile,
                                           const float* __restrict__ x) {
    // Copy ROWS contiguous x rows (64 KB) into smem buffer via cp.async.
    const char* src = (const char*)(x + (size_t)tile * TILE_F);
    unsigned dst = (unsigned)__cvta_generic_to_shared(smem + buf * TILE_F);
    constexpr int CP = TILE_F * 4 / 16 / THREADS;   // 4
#pragma unroll
    for (int i = 0; i < CP; i++) {
        int off = (threadIdx.x + i * THREADS) * 16;
        asm volatile("cp.async.cg.shared.global [%0], [%1], 16;\n"
                     :: "r"(dst + off), "l"(src + off));
    }
}

__global__ void __launch_bounds__(THREADS, 1)
logic_dense_kernel(const float* __restrict__ x,
                   const float* __restrict__ weight,
                   const int* __restrict__ idx_a,
                   const int* __restrict__ idx_b,
                   float* __restrict__ out) {
    constexpr int NT = BATCH / ROWS;   // 4096 tiles
    const int t0 = blockIdx.x;

    // Kick off the first two tile copies; they overlap the softmax prologue.
#pragma unroll
    for (int d = 0; d < 2; d++) {
        int t = t0 + d * GRID;
        if (t < NT) stage_tile(d, t, x);
        asm volatile("cp.async.commit_group;\n");
    }

    // Prologue: this thread's 8 columns' softmax -> gate coefficients + idx,
    // register-resident for the whole run.
    float4   c[COLS_PT];
    unsigned id[COLS_PT];
#pragma unroll
    for (int u = 0; u < COLS_PT; u++) {
        const int j = threadIdx.x + u * THREADS;
        const float4* wr = reinterpret_cast<const float4*>(weight + j * 16);
        float v[16];
#pragma unroll
        for (int q = 0; q < 4; q++) {
            float4 w4 = wr[q];
            v[q * 4 + 0] = w4.x; v[q * 4 + 1] = w4.y;
            v[q * 4 + 2] = w4.z; v[q * 4 + 3] = w4.w;
        }
        float m = v[0];
#pragma unroll
        for (int q = 1; q < 16; q++) m = fmaxf(m, v[q]);
        float s = 0.0f;
#pragma unroll
        for (int q = 0; q < 16; q++) { v[q] = expf(v[q] - m); s += v[q]; }
        const float inv = 1.0f / s;
        float c0 = 0.f, c1 = 0.f, c2 = 0.f, c3 = 0.f;
#pragma unroll
        for (int q = 0; q < 16; q++) {
            const float w = v[q] * inv;
            c0 = fmaf(w, GC[q][0], c0);
            c1 = fmaf(w, GC[q][1], c1);
            c2 = fmaf(w, GC[q][2], c2);
            c3 = fmaf(w, GC[q][3], c3);
        }
        c[u]  = make_float4(c0, c1, c2, c3);
        id[u] = (unsigned)idx_a[j] | ((unsigned)idx_b[j] << 13);
    }

    int bc = 0;                 // buffer consumed this iteration
    for (int t = t0; t < NT; t += GRID) {
        // 1) Retire THIS thread's copies of buffer bc (1 pending = tile t+1's
        //    group, still in flight).
        asm volatile("cp.async.wait_group 1;\n");
        // 2) Publish: every thread's copies of buffer bc are retired, and
        //    every thread has finished reading the buffer we restage below
        //    (it was consumed in the previous iteration).
        __syncthreads();

        // 3) Stage tile t + 2*GRID into buffer (bc+2)%3.
        int bs = bc + 2; if (bs >= NBUF) bs -= NBUF;
        const int ts = t + 2 * GRID;
        if (ts < NT) stage_tile(bs, ts, x);
        asm volatile("cp.async.commit_group;\n");

        // 4) Consume buffer bc.
        const float* __restrict__ buf = smem + bc * TILE_F;
        float* __restrict__ outr = out + (size_t)t * TILE_F;

#pragma unroll
        for (int u = 0; u < COLS_PT; u++) {
            const int j  = threadIdx.x + u * THREADS;
            const int ia = id[u] & 0x1FFF;
            const int ib = id[u] >> 13;
#pragma unroll
            for (int r = 0; r < ROWS; r++) {
                const float a = buf[r * IN_DIM + ia];
                const float b = buf[r * IN_DIM + ib];
                const float p = fmaf(c[u].w, a, c[u].z);
                const float q = fmaf(c[u].y, a, c[u].x);
                outr[r * OUT_DIM + j] = fmaf(b, p, q);
            }
        }

        if (++bc == NBUF) bc = 0;
    }
}

extern "C" void kernel_launch(void* const* d_in, const int* in_sizes, int n_in,
                              void* d_out, int out_size) {
    const float* x      = (const float*)d_in[0];
    const float* weight = (const float*)d_in[1];
    const int*   idx_a  = (const int*)d_in[2];
    const int*   idx_b  = (const int*)d_in[3];
    float*       out    = (float*)d_out;

    (void)in_sizes; (void)n_in; (void)out_size;

    const int smem_bytes = NBUF * TILE_F * (int)sizeof(float);   // 196608
    cudaFuncSetAttribute(logic_dense_kernel,
                         cudaFuncAttributeMaxDynamicSharedMemorySize,
                         smem_bytes);
    logic_dense_kernel<<<GRID, THREADS, smem_bytes>>>(x, weight, idx_a, idx_b,
                                                      out);
}